// round 11
// baseline (speedup 1.0000x reference)
#include <cuda_runtime.h>
#include <cuda_bf16.h>
#include <math.h>
#include <stdint.h>

#define N_VECS 8192
#define DIM    256
#define NCODES 8192
#define BM 128
#define BN 128
#define BK 64
#define NPANEL 3               // (Ahi,Bhi) (Ahi,Blo) (Alo,Bhi)
#define KITERS (NPANEL * (DIM / BK))   // 12
#define ROWB 144               // padded smem row stride (bytes) for 128B of data
#define TILE_SM (BM * ROWB)    // 18432
#define NSTG 3                 // 3-deep stage ring
#define STG2 (2 * TILE_SM)     // A tile + B tile per stage
#define SMEM_DYN (NSTG * STG2) // 110592
#define CCHUNKS (NCODES / BN)  // 64 column chunks
#define FINAL_BLOCKS 16

// ---- device scratch --------------------------------------------------------
__device__ __align__(16) unsigned g_Ahi[N_VECS * DIM / 2];   // 4MB each (bf16 pairs)
__device__ __align__(16) unsigned g_Alo[N_VECS * DIM / 2];
__device__ __align__(16) unsigned g_Bhi[NCODES * DIM / 2];
__device__ __align__(16) unsigned g_Blo[NCODES * DIM / 2];
__device__ float g_enorm[NCODES];                 // -0.5*||e||^2
__device__ float g_pval[CCHUNKS * N_VECS];        // per-column-chunk partial (-best)
__device__ int   g_pidx[CCHUNKS * N_VECS];
__device__ int   g_counts[NCODES];
__device__ float g_rowsum[N_VECS];
__device__ unsigned long long g_acc_sum;          // fixed point 2^24
__device__ unsigned long long g_acc_ent;          // fixed point 2^40 (two's complement)
__device__ int g_done;

__device__ __forceinline__ uint32_t s2u(const void* p) {
    uint32_t a;
    asm("{ .reg .u64 t; cvta.to.shared.u64 t, %1; cvt.u32.u64 %0, t; }" : "=r"(a) : "l"(p));
    return a;
}

// ---------------------------------------------------------------------------
// Pack: bf16 hi/lo split panels (row-major) + -0.5||e||^2, zero histogram.
// ---------------------------------------------------------------------------
__device__ __forceinline__ unsigned pk2(float a, float b) {
    __nv_bfloat16 ha = __float2bfloat16_rn(a), hb = __float2bfloat16_rn(b);
    unsigned short ua = *(unsigned short*)&ha, ub = *(unsigned short*)&hb;
    return (unsigned)ua | ((unsigned)ub << 16);
}
__global__ void pack_kernel(const float* __restrict__ X, const float* __restrict__ CB) {
    int m = blockIdx.x, t = threadIdx.x;
    float2 xv = *(const float2*)(X + (size_t)m * DIM + 2 * t);
    __nv_bfloat16 h0 = __float2bfloat16_rn(xv.x), h1 = __float2bfloat16_rn(xv.y);
    g_Ahi[m * 128 + t] = pk2(xv.x, xv.y);
    g_Alo[m * 128 + t] = pk2(xv.x - __bfloat162float(h0), xv.y - __bfloat162float(h1));

    float2 cv = *(const float2*)(CB + (size_t)m * DIM + 2 * t);
    __nv_bfloat16 c0 = __float2bfloat16_rn(cv.x), c1 = __float2bfloat16_rn(cv.y);
    g_Bhi[m * 128 + t] = pk2(cv.x, cv.y);
    g_Blo[m * 128 + t] = pk2(cv.x - __bfloat162float(c0), cv.y - __bfloat162float(c1));

    float s = cv.x * cv.x + cv.y * cv.y;
#pragma unroll
    for (int o = 16; o; o >>= 1) s += __shfl_xor_sync(~0u, s, o);
    __shared__ float sw[4];
    if ((t & 31) == 0) sw[t >> 5] = s;
    __syncthreads();
    if (t == 0) {
        g_enorm[m] = -0.5f * (sw[0] + sw[1] + sw[2] + sw[3]);
        g_counts[m] = 0;
        if (m == 0) { g_acc_sum = 0ull; g_acc_ent = 0ull; g_done = 0; }
    }
}

// ---------------------------------------------------------------------------
// Main: bf16 mma.sync GEMM (3 split panels, sequential) + fused argmax.
// grid = (64 col-chunks, 64 row-tiles), 128 threads = 4 warps (2 M x 2 N).
// Warp tile 64x64, thread accums 4x8x4 = 128 fp32. BK=64, 3-stage ring.
// ---------------------------------------------------------------------------
__global__ void __launch_bounds__(128, 2) vq_main() {
    extern __shared__ __align__(16) unsigned char dynsm[];

    const int tid  = threadIdx.x;
    const int lane = tid & 31, wid = tid >> 5;
    const int wm = wid >> 1, wn = wid & 1;          // 2 x 2 warp grid
    const int brow0 = blockIdx.y * BM;
    const int bcol0 = blockIdx.x * BN;
    const uint32_t base = s2u(dynsm);

    float acc[4][8][4];
#pragma unroll
    for (int i = 0; i < 4; i++)
#pragma unroll
        for (int j = 0; j < 8; j++)
#pragma unroll
            for (int r = 0; r < 4; r++) acc[i][j][r] = 0.f;

    // ---- async stage of one BK=64 slice (A tile + B tile) into stage s ----
    auto stage = [&](int s, int it) {
        int p = it >> 2, kb = (it & 3) * 128;       // byte offset of 64-elem chunk
        const char* Ab = (const char*)(p < 2 ? g_Ahi : g_Alo);
        const char* Bb = (const char*)(p == 1 ? g_Blo : g_Bhi);
        uint32_t sg = base + s * STG2;
#pragma unroll
        for (int l = 0; l < 8; l++) {
            int c = tid + l * 128;                  // 0..1023
            int row = c >> 3, sub = c & 7;          // 8 x 16B per 128B row-slice
            uint32_t da = sg + row * ROWB + sub * 16;
            const char* srcA = Ab + (size_t)(brow0 + row) * 512 + kb + sub * 16;
            asm volatile("cp.async.cg.shared.global [%0], [%1], 16;" :: "r"(da), "l"(srcA) : "memory");
            uint32_t db = sg + TILE_SM + row * ROWB + sub * 16;
            const char* srcB = Bb + (size_t)(bcol0 + row) * 512 + kb + sub * 16;
            asm volatile("cp.async.cg.shared.global [%0], [%1], 16;" :: "r"(db), "l"(srcB) : "memory");
        }
        asm volatile("cp.async.commit_group;" ::: "memory");
    };

    stage(0, 0);
    stage(1, 1);

    int sidx = 0;
    for (int it = 0; it < KITERS; it++) {
        if (it + 2 < KITERS) {
            stage((sidx + 2) % NSTG, it + 2);
            asm volatile("cp.async.wait_group 2;" ::: "memory");
        } else if (it + 1 < KITERS) {
            asm volatile("cp.async.wait_group 1;" ::: "memory");
        } else {
            asm volatile("cp.async.wait_group 0;" ::: "memory");
        }
        __syncthreads();

        const uint32_t Abase = base + sidx * STG2;
        const uint32_t Bbase = Abase + TILE_SM;
#pragma unroll
        for (int kk = 0; kk < 4; kk++) {            // four k16 steps per BK=64
            uint32_t a[4][4];
#pragma unroll
            for (int mi = 0; mi < 4; mi++) {
                int rowA = wm * 64 + mi * 16 + (lane & 15);
                uint32_t ad = Abase + rowA * ROWB + kk * 32 + (lane >> 4) * 16;
                asm volatile("ldmatrix.sync.aligned.m8n8.x4.shared.b16 {%0,%1,%2,%3}, [%4];"
                             : "=r"(a[mi][0]), "=r"(a[mi][1]), "=r"(a[mi][2]), "=r"(a[mi][3])
                             : "r"(ad));
            }
            uint32_t b[8][2];
#pragma unroll
            for (int nip = 0; nip < 4; nip++) {     // 2 n8-tiles per ldmatrix.x4
                int rowB = wn * 64 + nip * 16 + (lane & 7) + ((lane >> 4) << 3);
                uint32_t bd = Bbase + rowB * ROWB + kk * 32 + (((lane >> 3) & 1) * 16);
                uint32_t r0, r1, r2, r3;
                asm volatile("ldmatrix.sync.aligned.m8n8.x4.shared.b16 {%0,%1,%2,%3}, [%4];"
                             : "=r"(r0), "=r"(r1), "=r"(r2), "=r"(r3) : "r"(bd));
                b[nip * 2][0] = r0;     b[nip * 2][1] = r1;
                b[nip * 2 + 1][0] = r2; b[nip * 2 + 1][1] = r3;
            }
#pragma unroll
            for (int mi = 0; mi < 4; mi++)
#pragma unroll
                for (int ni = 0; ni < 8; ni++) {
                    asm volatile(
                        "mma.sync.aligned.m16n8k16.row.col.f32.bf16.bf16.f32 "
                        "{%0,%1,%2,%3}, {%4,%5,%6,%7}, {%8,%9}, {%0,%1,%2,%3};"
                        : "+f"(acc[mi][ni][0]), "+f"(acc[mi][ni][1]),
                          "+f"(acc[mi][ni][2]), "+f"(acc[mi][ni][3])
                        : "r"(a[mi][0]), "r"(a[mi][1]), "r"(a[mi][2]), "r"(a[mi][3]),
                          "r"(b[ni][0]), "r"(b[ni][1]));
                }
        }
        __syncthreads();
        sidx = (sidx + 1) % NSTG;
    }

    // ---- epilogue (aliases stage memory; all MMA reads done, synced above) --
    float* en_s = (float*)dynsm;                 // 128 floats
    float* svp  = (float*)(dynsm + 512);         // 128 x 2
    int*   sip  = (int*)(dynsm + 1536);          // 128 x 2
    en_s[tid] = g_enorm[bcol0 + tid];
    __syncthreads();

    const int g = lane >> 2, q = lane & 3;
#pragma unroll
    for (int mi = 0; mi < 4; mi++) {
        float bv0 = -3.402823466e38f, bv1 = -3.402823466e38f;
        int bi0 = 0, bi1 = 0;
#pragma unroll
        for (int ni = 0; ni < 8; ni++) {
            int nl = wn * 64 + ni * 8 + q * 2;      // local col of d0/d2
#pragma unroll
            for (int c = 0; c < 2; c++) {           // ascending col within pair
                float e = en_s[nl + c];
                float v0 = acc[mi][ni][c] + e;       // row g
                float v1 = acc[mi][ni][c + 2] + e;   // row g+8
                int col = bcol0 + nl + c;
                if (v0 > bv0) { bv0 = v0; bi0 = col; }
                if (v1 > bv1) { bv1 = v1; bi1 = col; }
            }
        }
#pragma unroll
        for (int o = 1; o <= 2; o <<= 1) {
            float ov = __shfl_xor_sync(~0u, bv0, o); int oi = __shfl_xor_sync(~0u, bi0, o);
            if (ov > bv0 || (ov == bv0 && oi < bi0)) { bv0 = ov; bi0 = oi; }
            ov = __shfl_xor_sync(~0u, bv1, o); oi = __shfl_xor_sync(~0u, bi1, o);
            if (ov > bv1 || (ov == bv1 && oi < bi1)) { bv1 = ov; bi1 = oi; }
        }
        if (q == 0) {
            int r0 = wm * 64 + mi * 16 + g;
            svp[r0 * 2 + wn] = bv0; sip[r0 * 2 + wn] = bi0;
            svp[(r0 + 8) * 2 + wn] = bv1; sip[(r0 + 8) * 2 + wn] = bi1;
        }
    }
    __syncthreads();
    {
        float bv = svp[tid * 2]; int bi = sip[tid * 2];
        float v = svp[tid * 2 + 1]; int i = sip[tid * 2 + 1];
        if (v > bv || (v == bv && i < bi)) { bv = v; bi = i; }
        g_pval[blockIdx.x * N_VECS + brow0 + tid] = -bv;   // monotone image of distance
        g_pidx[blockIdx.x * N_VECS + brow0 + tid] = bi;
    }
}

// ---------------------------------------------------------------------------
// Gather: reduce 64 column-chunk partials per row (exact first-min ties),
// write quantized row, per-row SSE, deterministic histogram. 1 warp/row.
// ---------------------------------------------------------------------------
__global__ void gather_kernel(const float* __restrict__ X,
                              const float* __restrict__ CB,
                              float* __restrict__ out) {
    int row  = blockIdx.x * 8 + (threadIdx.x >> 5);
    int lane = threadIdx.x & 31;

    float bv = g_pval[lane * N_VECS + row];
    int   bi = g_pidx[lane * N_VECS + row];
    {
        float v = g_pval[(lane + 32) * N_VECS + row];
        int   i = g_pidx[(lane + 32) * N_VECS + row];
        if (v < bv || (v == bv && i < bi)) { bv = v; bi = i; }
    }
#pragma unroll
    for (int o = 16; o > 0; o >>= 1) {
        float ov = __shfl_xor_sync(~0u, bv, o);
        int   oi = __shfl_xor_sync(~0u, bi, o);
        if (ov < bv || (ov == bv && oi < bi)) { bv = ov; bi = oi; }
    }

    const float4* e = (const float4*)(CB + (size_t)bi * DIM);
    const float4* x = (const float4*)(X + (size_t)row * DIM);
    float4* o4 = (float4*)(out + (size_t)row * DIM);
    float s = 0.f;
#pragma unroll
    for (int i = 0; i < 2; i++) {
        float4 ev = e[lane + 32 * i];
        float4 xv = x[lane + 32 * i];
        o4[lane + 32 * i] = ev;
        float d;
        d = ev.x - xv.x; s += d * d;
        d = ev.y - xv.y; s += d * d;
        d = ev.z - xv.z; s += d * d;
        d = ev.w - xv.w; s += d * d;
    }
#pragma unroll
    for (int off = 16; off > 0; off >>= 1) s += __shfl_xor_sync(0xffffffffu, s, off);
    if (lane == 0) {
        g_rowsum[row] = s;
        atomicAdd(&g_counts[bi], 1);
    }
}

// ---------------------------------------------------------------------------
// Finalize: 16 blocks, deterministic fixed-point i64 atomics, last block
// writes the two scalars. (Counters reset in pack_kernel each replay.)
// ---------------------------------------------------------------------------
__global__ void finalize_kernel(float* __restrict__ out, int qelems) {
    __shared__ float shs[8], she[8];
    int t = blockIdx.x * 256 + threadIdx.x;       // 4096 threads total
    int lane = threadIdx.x & 31, w = threadIdx.x >> 5;

    float s = 0.f, ent = 0.f;
    for (int i = t; i < N_VECS; i += FINAL_BLOCKS * 256) s += g_rowsum[i];
    for (int i = t; i < NCODES; i += FINAL_BLOCKS * 256) {
        int c = g_counts[i];
        if (c) {
            float p = (float)c * (1.0f / (float)N_VECS);
            ent += p * logf(p + 1e-10f);
        }
    }
#pragma unroll
    for (int o = 16; o; o >>= 1) { s += __shfl_xor_sync(~0u, s, o); ent += __shfl_xor_sync(~0u, ent, o); }
    if (lane == 0) { shs[w] = s; she[w] = ent; }
    __syncthreads();
    if (threadIdx.x == 0) {
        float bs = 0.f, be = 0.f;
#pragma unroll
        for (int i = 0; i < 8; i++) { bs += shs[i]; be += she[i]; }
        atomicAdd(&g_acc_sum, (unsigned long long)__float2ll_rn(bs * 16777216.f));        // 2^24
        atomicAdd(&g_acc_ent, (unsigned long long)__float2ll_rn(be * 1099511627776.f));   // 2^40
        __threadfence();
        int prev = atomicAdd(&g_done, 1);
        if (prev == FINAL_BLOCKS - 1) {
            float total = (float)(long long)g_acc_sum * (1.f / 16777216.f);
            float e2    = (float)(long long)g_acc_ent * (1.f / 1099511627776.f);
            float mse = total / (float)((size_t)N_VECS * DIM);
            out[qelems]     = 1.25f * mse;
            out[qelems + 1] = expf(-e2);
        }
    }
}

// ---------------------------------------------------------------------------
extern "C" void kernel_launch(void* const* d_in, const int* in_sizes, int n_in,
                              void* d_out, int out_size) {
    const float* X  = (const float*)d_in[0];
    const float* CB = (const float*)d_in[1];
    float* out = (float*)d_out;

    pack_kernel<<<8192, 128>>>(X, CB);
    cudaFuncSetAttribute(vq_main, cudaFuncAttributeMaxDynamicSharedMemorySize, SMEM_DYN);
    dim3 grid(CCHUNKS, N_VECS / BM);     // (64 col chunks, 64 row tiles)
    vq_main<<<grid, 128, SMEM_DYN>>>();
    gather_kernel<<<N_VECS / 8, 256>>>(X, CB, out);
    finalize_kernel<<<FINAL_BLOCKS, 256>>>(out, out_size - 2);
}

// round 13
// speedup vs baseline: 1.1240x; 1.1240x over previous
#include <cuda_runtime.h>
#include <cuda_bf16.h>
#include <math.h>
#include <stdint.h>

#define N_VECS 8192
#define DIM    256
#define NCODES 8192
#define BM 128
#define BN 128
#define BK 64
#define NPANEL 3               // (Ahi,Bhi) (Ahi,Blo) (Alo,Bhi)
#define KITERS (NPANEL * (DIM / BK))   // 12
#define ROWB 144               // padded smem row stride (bytes) for 128B of data
#define TILE_SM (BM * ROWB)    // 18432
#define SMEM_DYN (4 * TILE_SM) // 73728: sA0,sA1,sB0,sB1
#define CCHUNKS (NCODES / BN)  // 64 column chunks
#define FINAL_BLOCKS 16

// ---- device scratch --------------------------------------------------------
__device__ __align__(16) unsigned g_Ahi[N_VECS * DIM / 2];   // 4MB each (bf16 pairs)
__device__ __align__(16) unsigned g_Alo[N_VECS * DIM / 2];
__device__ __align__(16) unsigned g_Bhi[NCODES * DIM / 2];
__device__ __align__(16) unsigned g_Blo[NCODES * DIM / 2];
__device__ float g_enorm[NCODES];                 // -0.5*||e||^2
__device__ float g_pval[CCHUNKS * N_VECS];        // per-column-chunk partial (-best)
__device__ int   g_pidx[CCHUNKS * N_VECS];
__device__ int   g_counts[NCODES];
__device__ float g_rowsum[N_VECS];
__device__ unsigned long long g_acc_sum;          // fixed point 2^24
__device__ unsigned long long g_acc_ent;          // fixed point 2^40 (two's complement)
__device__ int g_done;

__device__ __forceinline__ uint32_t s2u(const void* p) {
    uint32_t a;
    asm("{ .reg .u64 t; cvta.to.shared.u64 t, %1; cvt.u32.u64 %0, t; }" : "=r"(a) : "l"(p));
    return a;
}

// ---------------------------------------------------------------------------
// Pack: bf16 hi/lo split panels (row-major) + -0.5||e||^2, zero histogram.
// ---------------------------------------------------------------------------
__device__ __forceinline__ unsigned pk2(float a, float b) {
    __nv_bfloat16 ha = __float2bfloat16_rn(a), hb = __float2bfloat16_rn(b);
    unsigned short ua = *(unsigned short*)&ha, ub = *(unsigned short*)&hb;
    return (unsigned)ua | ((unsigned)ub << 16);
}
__global__ void pack_kernel(const float* __restrict__ X, const float* __restrict__ CB) {
    int m = blockIdx.x, t = threadIdx.x;
    float2 xv = *(const float2*)(X + (size_t)m * DIM + 2 * t);
    __nv_bfloat16 h0 = __float2bfloat16_rn(xv.x), h1 = __float2bfloat16_rn(xv.y);
    g_Ahi[m * 128 + t] = pk2(xv.x, xv.y);
    g_Alo[m * 128 + t] = pk2(xv.x - __bfloat162float(h0), xv.y - __bfloat162float(h1));

    float2 cv = *(const float2*)(CB + (size_t)m * DIM + 2 * t);
    __nv_bfloat16 c0 = __float2bfloat16_rn(cv.x), c1 = __float2bfloat16_rn(cv.y);
    g_Bhi[m * 128 + t] = pk2(cv.x, cv.y);
    g_Blo[m * 128 + t] = pk2(cv.x - __bfloat162float(c0), cv.y - __bfloat162float(c1));

    float s = cv.x * cv.x + cv.y * cv.y;
#pragma unroll
    for (int o = 16; o; o >>= 1) s += __shfl_xor_sync(~0u, s, o);
    __shared__ float sw[4];
    if ((t & 31) == 0) sw[t >> 5] = s;
    __syncthreads();
    if (t == 0) {
        g_enorm[m] = -0.5f * (sw[0] + sw[1] + sw[2] + sw[3]);
        g_counts[m] = 0;
        if (m == 0) { g_acc_sum = 0ull; g_acc_ent = 0ull; g_done = 0; }
    }
}

// ---------------------------------------------------------------------------
// Main: bf16 mma.sync GEMM (3 split panels) + fused per-row argmax.
// grid = (64 col-chunks, 64 row-tiles), 128 threads = 4 warps (2 M x 2 N).
// Warp tile 64x64, thread accums 4x8x4 = 128 fp32. BK=64 double-buffered.
// (Exact R8 schedule — measured 260.2 us.)
// ---------------------------------------------------------------------------
__global__ void __launch_bounds__(128, 2) vq_main() {
    extern __shared__ __align__(16) unsigned char dynsm[];
    __shared__ float en_s[BN];
    __shared__ float sv[BM][2];
    __shared__ int   si[BM][2];

    const int tid  = threadIdx.x;
    const int lane = tid & 31, wid = tid >> 5;
    const int wm = wid >> 1, wn = wid & 1;          // 2 x 2 warp grid
    const int brow0 = blockIdx.y * BM;
    const int bcol0 = blockIdx.x * BN;

    const uint32_t base = s2u(dynsm);
    const uint32_t sAu[2] = { base, base + TILE_SM };
    const uint32_t sBu[2] = { base + 2 * TILE_SM, base + 3 * TILE_SM };

    float acc[4][8][4];
#pragma unroll
    for (int i = 0; i < 4; i++)
#pragma unroll
        for (int j = 0; j < 8; j++)
#pragma unroll
            for (int r = 0; r < 4; r++) acc[i][j][r] = 0.f;

    // ---- async stage of one BK=64 slice into buffer `buf` ----
    auto stage = [&](int buf, int it) {
        int p = it >> 2, kb = (it & 3) * 128;       // byte offset of 64-elem chunk
        const char* Ab = (const char*)(p < 2 ? g_Ahi : g_Alo);
        const char* Bb = (const char*)(p == 1 ? g_Blo : g_Bhi);
#pragma unroll
        for (int l = 0; l < 8; l++) {
            int c = tid + l * 128;                  // 0..1023
            int row = c >> 3, sub = c & 7;          // 8 x 16B per 128B row-slice
            uint32_t da = sAu[buf] + row * ROWB + sub * 16;
            const char* srcA = Ab + (size_t)(brow0 + row) * 512 + kb + sub * 16;
            asm volatile("cp.async.cg.shared.global [%0], [%1], 16;" :: "r"(da), "l"(srcA) : "memory");
            uint32_t db = sBu[buf] + row * ROWB + sub * 16;
            const char* srcB = Bb + (size_t)(bcol0 + row) * 512 + kb + sub * 16;
            asm volatile("cp.async.cg.shared.global [%0], [%1], 16;" :: "r"(db), "l"(srcB) : "memory");
        }
        asm volatile("cp.async.commit_group;" ::: "memory");
    };

    stage(0, 0);

    for (int it = 0; it < KITERS; it++) {
        int buf = it & 1;
        if (it < KITERS - 1) {
            stage(buf ^ 1, it + 1);
            asm volatile("cp.async.wait_group 1;" ::: "memory");
        } else {
            asm volatile("cp.async.wait_group 0;" ::: "memory");
        }
        __syncthreads();

        const uint32_t Abase = sAu[buf];
        const uint32_t Bbase = sBu[buf];
#pragma unroll
        for (int kk = 0; kk < 4; kk++) {            // four k16 steps per BK=64
            uint32_t a[4][4];
#pragma unroll
            for (int mi = 0; mi < 4; mi++) {
                int rowA = wm * 64 + mi * 16 + (lane & 15);
                uint32_t ad = Abase + rowA * ROWB + kk * 32 + (lane >> 4) * 16;
                asm volatile("ldmatrix.sync.aligned.m8n8.x4.shared.b16 {%0,%1,%2,%3}, [%4];"
                             : "=r"(a[mi][0]), "=r"(a[mi][1]), "=r"(a[mi][2]), "=r"(a[mi][3])
                             : "r"(ad));
            }
            uint32_t b[8][2];
#pragma unroll
            for (int nip = 0; nip < 4; nip++) {     // 2 n8-tiles per ldmatrix.x4
                int rowB = wn * 64 + nip * 16 + (lane & 7) + ((lane >> 4) << 3);
                uint32_t bd = Bbase + rowB * ROWB + kk * 32 + (((lane >> 3) & 1) * 16);
                uint32_t r0, r1, r2, r3;
                asm volatile("ldmatrix.sync.aligned.m8n8.x4.shared.b16 {%0,%1,%2,%3}, [%4];"
                             : "=r"(r0), "=r"(r1), "=r"(r2), "=r"(r3) : "r"(bd));
                b[nip * 2][0] = r0;     b[nip * 2][1] = r1;
                b[nip * 2 + 1][0] = r2; b[nip * 2 + 1][1] = r3;
            }
#pragma unroll
            for (int mi = 0; mi < 4; mi++)
#pragma unroll
                for (int ni = 0; ni < 8; ni++) {
                    asm volatile(
                        "mma.sync.aligned.m16n8k16.row.col.f32.bf16.bf16.f32 "
                        "{%0,%1,%2,%3}, {%4,%5,%6,%7}, {%8,%9}, {%0,%1,%2,%3};"
                        : "+f"(acc[mi][ni][0]), "+f"(acc[mi][ni][1]),
                          "+f"(acc[mi][ni][2]), "+f"(acc[mi][ni][3])
                        : "r"(a[mi][0]), "r"(a[mi][1]), "r"(a[mi][2]), "r"(a[mi][3]),
                          "r"(b[ni][0]), "r"(b[ni][1]));
                }
        }
        __syncthreads();
    }

    // ---- epilogue: add -0.5||e||^2, per-row argmax, exact first-min ties ----
    en_s[tid] = g_enorm[bcol0 + tid];
    __syncthreads();

    const int g = lane >> 2, q = lane & 3;
#pragma unroll
    for (int mi = 0; mi < 4; mi++) {
        float bv0 = -3.402823466e38f, bv1 = -3.402823466e38f;
        int bi0 = 0, bi1 = 0;
#pragma unroll
        for (int ni = 0; ni < 8; ni++) {
            int nl = wn * 64 + ni * 8 + q * 2;      // local col of d0/d2
#pragma unroll
            for (int c = 0; c < 2; c++) {           // ascending col within pair
                float e = en_s[nl + c];
                float v0 = acc[mi][ni][c] + e;       // row g
                float v1 = acc[mi][ni][c + 2] + e;   // row g+8
                int col = bcol0 + nl + c;
                if (v0 > bv0) { bv0 = v0; bi0 = col; }
                if (v1 > bv1) { bv1 = v1; bi1 = col; }
            }
        }
        // reduce across the 4 lanes of the quad (same rows)
#pragma unroll
        for (int o = 1; o <= 2; o <<= 1) {
            float ov = __shfl_xor_sync(~0u, bv0, o); int oi = __shfl_xor_sync(~0u, bi0, o);
            if (ov > bv0 || (ov == bv0 && oi < bi0)) { bv0 = ov; bi0 = oi; }
            ov = __shfl_xor_sync(~0u, bv1, o); oi = __shfl_xor_sync(~0u, bi1, o);
            if (ov > bv1 || (ov == bv1 && oi < bi1)) { bv1 = ov; bi1 = oi; }
        }
        if (q == 0) {
            int r0 = wm * 64 + mi * 16 + g;
            sv[r0][wn] = bv0; si[r0][wn] = bi0;
            sv[r0 + 8][wn] = bv1; si[r0 + 8][wn] = bi1;
        }
    }
    __syncthreads();
    {
        float bv = sv[tid][0]; int bi = si[tid][0];
        float v = sv[tid][1];  int i = si[tid][1];
        if (v > bv || (v == bv && i < bi)) { bv = v; bi = i; }
        g_pval[blockIdx.x * N_VECS + brow0 + tid] = -bv;   // monotone image of distance
        g_pidx[blockIdx.x * N_VECS + brow0 + tid] = bi;
    }
}

// ---------------------------------------------------------------------------
// Gather: reduce 64 column-chunk partials per row (exact first-min ties),
// write quantized row, per-row SSE, deterministic histogram. 1 warp/row.
// ---------------------------------------------------------------------------
__global__ void gather_kernel(const float* __restrict__ X,
                              const float* __restrict__ CB,
                              float* __restrict__ out) {
    int row  = blockIdx.x * 8 + (threadIdx.x >> 5);
    int lane = threadIdx.x & 31;

    float bv = g_pval[lane * N_VECS + row];
    int   bi = g_pidx[lane * N_VECS + row];
    {
        float v = g_pval[(lane + 32) * N_VECS + row];
        int   i = g_pidx[(lane + 32) * N_VECS + row];
        if (v < bv || (v == bv && i < bi)) { bv = v; bi = i; }
    }
#pragma unroll
    for (int o = 16; o > 0; o >>= 1) {
        float ov = __shfl_xor_sync(~0u, bv, o);
        int   oi = __shfl_xor_sync(~0u, bi, o);
        if (ov < bv || (ov == bv && oi < bi)) { bv = ov; bi = oi; }
    }

    const float4* e = (const float4*)(CB + (size_t)bi * DIM);
    const float4* x = (const float4*)(X + (size_t)row * DIM);
    float4* o4 = (float4*)(out + (size_t)row * DIM);
    float s = 0.f;
#pragma unroll
    for (int i = 0; i < 2; i++) {
        float4 ev = e[lane + 32 * i];
        float4 xv = x[lane + 32 * i];
        o4[lane + 32 * i] = ev;
        float d;
        d = ev.x - xv.x; s += d * d;
        d = ev.y - xv.y; s += d * d;
        d = ev.z - xv.z; s += d * d;
        d = ev.w - xv.w; s += d * d;
    }
#pragma unroll
    for (int off = 16; off > 0; off >>= 1) s += __shfl_xor_sync(0xffffffffu, s, off);
    if (lane == 0) {
        g_rowsum[row] = s;
        atomicAdd(&g_counts[bi], 1);
    }
}

// ---------------------------------------------------------------------------
// Finalize: 16 blocks, deterministic fixed-point i64 atomics, last block
// writes the two scalars. (Counters reset in pack_kernel each replay.)
// ---------------------------------------------------------------------------
__global__ void finalize_kernel(float* __restrict__ out, int qelems) {
    __shared__ float shs[8], she[8];
    int t = blockIdx.x * 256 + threadIdx.x;       // 4096 threads total
    int lane = threadIdx.x & 31, w = threadIdx.x >> 5;

    float s = 0.f, ent = 0.f;
    for (int i = t; i < N_VECS; i += FINAL_BLOCKS * 256) s += g_rowsum[i];
    for (int i = t; i < NCODES; i += FINAL_BLOCKS * 256) {
        int c = g_counts[i];
        if (c) {
            float p = (float)c * (1.0f / (float)N_VECS);
            ent += p * logf(p + 1e-10f);
        }
    }
#pragma unroll
    for (int o = 16; o; o >>= 1) { s += __shfl_xor_sync(~0u, s, o); ent += __shfl_xor_sync(~0u, ent, o); }
    if (lane == 0) { shs[w] = s; she[w] = ent; }
    __syncthreads();
    if (threadIdx.x == 0) {
        float bs = 0.f, be = 0.f;
#pragma unroll
        for (int i = 0; i < 8; i++) { bs += shs[i]; be += she[i]; }
        atomicAdd(&g_acc_sum, (unsigned long long)__float2ll_rn(bs * 16777216.f));        // 2^24
        atomicAdd(&g_acc_ent, (unsigned long long)__float2ll_rn(be * 1099511627776.f));   // 2^40
        __threadfence();
        int prev = atomicAdd(&g_done, 1);
        if (prev == FINAL_BLOCKS - 1) {
            float total = (float)(long long)g_acc_sum * (1.f / 16777216.f);
            float e2    = (float)(long long)g_acc_ent * (1.f / 1099511627776.f);
            float mse = total / (float)((size_t)N_VECS * DIM);
            out[qelems]     = 1.25f * mse;
            out[qelems + 1] = expf(-e2);
        }
    }
}

// ---------------------------------------------------------------------------
extern "C" void kernel_launch(void* const* d_in, const int* in_sizes, int n_in,
                              void* d_out, int out_size) {
    const float* X  = (const float*)d_in[0];
    const float* CB = (const float*)d_in[1];
    float* out = (float*)d_out;

    pack_kernel<<<8192, 128>>>(X, CB);
    cudaFuncSetAttribute(vq_main, cudaFuncAttributeMaxDynamicSharedMemorySize, SMEM_DYN);
    dim3 grid(CCHUNKS, N_VECS / BM);     // (64 col chunks, 64 row tiles)
    vq_main<<<grid, 128, SMEM_DYN>>>();
    gather_kernel<<<N_VECS / 8, 256>>>(X, CB, out);
    finalize_kernel<<<FINAL_BLOCKS, 256>>>(out, out_size - 2);
}